// round 4
// baseline (speedup 1.0000x reference)
#include <cuda_runtime.h>
#include <math.h>

#define S_LEN   3072
#define HIDDEN  2048
#define HQ      16
#define HK      2
#define D_HEAD  128
#define QCOLS   (HQ * D_HEAD)   // 2048
#define KCOLS   (HK * D_HEAD)   // 256
#define NSHARED 8

// ---------------- scratch (device globals: no allocations allowed) ----------
__device__ float g_Q[S_LEN * QCOLS];   // 24 MB
__device__ float g_K[S_LEN * KCOLS];   //  3 MB
__device__ float g_V[S_LEN * KCOLS];   //  3 MB
__device__ float g_A[S_LEN * QCOLS];   // 24 MB (attention output, pre-Wo)

// ============================================================================
// SGEMM: C[M,N] = A[M,K] * B[N,K]^T  (all row-major fp32)
// BM=BN=128, BK=8, 256 threads, 8x8 micro-tile with split-subtile mapping.
// Requires M%128==0, N%128==0, K%8==0 (true for all four calls here).
// ============================================================================
__global__ __launch_bounds__(256, 2)
void sgemm_nt(const float* __restrict__ A, const float* __restrict__ B,
              float* __restrict__ C, int M, int N, int K) {
    __shared__ float As[8][132];
    __shared__ float Bs[8][132];

    const int t  = threadIdx.x;
    const int tx = t & 15;
    const int ty = t >> 4;
    const int bm = blockIdx.y * 128;
    const int bn = blockIdx.x * 128;

    const int arow = t >> 1;          // 0..127
    const int akq  = (t & 1) * 4;     // 0 or 4

    const float* Ag = A + (size_t)(bm + arow) * K + akq;
    const float* Bg = B + (size_t)(bn + arow) * K + akq;

    float acc[8][8];
#pragma unroll
    for (int i = 0; i < 8; i++)
#pragma unroll
        for (int j = 0; j < 8; j++) acc[i][j] = 0.0f;

    for (int k0 = 0; k0 < K; k0 += 8) {
        float4 av = *(const float4*)(Ag + k0);
        float4 bv = *(const float4*)(Bg + k0);
        As[akq + 0][arow] = av.x; As[akq + 1][arow] = av.y;
        As[akq + 2][arow] = av.z; As[akq + 3][arow] = av.w;
        Bs[akq + 0][arow] = bv.x; Bs[akq + 1][arow] = bv.y;
        Bs[akq + 2][arow] = bv.z; Bs[akq + 3][arow] = bv.w;
        __syncthreads();

#pragma unroll
        for (int k = 0; k < 8; k++) {
            float4 a0 = *(const float4*)&As[k][ty * 4];
            float4 a1 = *(const float4*)&As[k][64 + ty * 4];
            float4 b0 = *(const float4*)&Bs[k][tx * 4];
            float4 b1 = *(const float4*)&Bs[k][64 + tx * 4];
            float ar[8] = {a0.x, a0.y, a0.z, a0.w, a1.x, a1.y, a1.z, a1.w};
            float br[8] = {b0.x, b0.y, b0.z, b0.w, b1.x, b1.y, b1.z, b1.w};
#pragma unroll
            for (int i = 0; i < 8; i++)
#pragma unroll
                for (int j = 0; j < 8; j++)
                    acc[i][j] += ar[i] * br[j];
        }
        __syncthreads();
    }

#pragma unroll
    for (int i = 0; i < 8; i++) {
        int r = bm + ((i < 4) ? (ty * 4 + i) : (64 + ty * 4 + i - 4));
        *(float4*)&C[(size_t)r * N + bn + tx * 4] =
            make_float4(acc[i][0], acc[i][1], acc[i][2], acc[i][3]);
        *(float4*)&C[(size_t)r * N + bn + 64 + tx * 4] =
            make_float4(acc[i][4], acc[i][5], acc[i][6], acc[i][7]);
    }
}

// ============================================================================
// RoPE in-place. One thread per rotation pair (s, head, fi<64).
// out[d]    = x[d]*cos(p*invf) - x[d+64]*sin(p*invf)
// out[d+64] = x[d+64]*cos(...) + x[d]*sin(...)
// ============================================================================
__global__ void rope_kernel(float* __restrict__ x, const int* __restrict__ pos,
                            int nheads, int total) {
    int idx = blockIdx.x * blockDim.x + threadIdx.x;
    if (idx >= total) return;
    int fi = idx & 63;
    int h  = (idx >> 6) % nheads;
    int s  = idx / (nheads * 64);

    float p    = (float)pos[s];
    float invf = powf(10000.0f, -((float)fi) / 64.0f);
    float sn, cs;
    sincosf(p * invf, &sn, &cs);   // accurate range reduction (angle up to ~3071)

    size_t base = (size_t)s * (nheads * D_HEAD) + h * D_HEAD + fi;
    float x1 = x[base];
    float x2 = x[base + 64];
    x[base]      = x1 * cs - x2 * sn;
    x[base + 64] = x2 * cs + x1 * sn;
}

// ============================================================================
// Flash attention, fp32, causal. Block = (q-tile of 64, head). 256 threads.
// Smem: Qs[64][132] + KVs[64][132] (K then reused for V) + Ps[64][72].
// Thread (ty,tx): score micro-tile = q-rows ty*4..+3 x k-cols tx*4..+3.
// Online softmax with 16-lane shuffle reductions (tx lanes share a q-row).
// GQA mapping: reference uses jnp.tile (whole-block repeat), so
// q-head h -> kv-head (h % HK) == (h & 1).  NOT h / NSHARED.
// ============================================================================
#define SMEM_FLASH ((2 * 64 * 132 + 64 * 72) * 4)   // 86016 bytes

__global__ __launch_bounds__(256, 2)
void flash_kernel(const float* __restrict__ Q, const float* __restrict__ Kb,
                  const float* __restrict__ Vb, float* __restrict__ O) {
    extern __shared__ float sm[];
    float* Qs  = sm;                  // [64][132]
    float* KVs = sm + 64 * 132;       // [64][132]
    float* Ps  = sm + 2 * 64 * 132;   // [64][72]

    const int t  = threadIdx.x;
    const int tx = t & 15;
    const int ty = t >> 4;
    const int qt = gridDim.x - 1 - blockIdx.x;   // longest blocks launch first
    const int h  = blockIdx.y;
    const int q0 = qt * 64;
    const int kvoff = (h & 1) * D_HEAD;          // GQA: kv head = h % HK (tile!)

    // ---- load Q tile (64 x 128) into smem ----
#pragma unroll
    for (int i = 0; i < 8; i++) {
        int idx = t + i * 256;
        int r   = idx >> 5;
        int d4  = (idx & 31) << 2;
        *(float4*)&Qs[r * 132 + d4] =
            *(const float4*)&Q[(size_t)(q0 + r) * QCOLS + h * D_HEAD + d4];
    }

    float m_r[4], l_r[4], o_r[4][8];
#pragma unroll
    for (int r = 0; r < 4; r++) {
        m_r[r] = -INFINITY;
        l_r[r] = 0.0f;
#pragma unroll
        for (int j = 0; j < 8; j++) o_r[r][j] = 0.0f;
    }

    const float scale = 0.08838834764831845f;   // 1/sqrt(128)

    for (int kt = 0; kt <= qt; kt++) {
        const int k0 = kt * 64;

        // ---- load K tile ----
#pragma unroll
        for (int i = 0; i < 8; i++) {
            int idx = t + i * 256;
            int r   = idx >> 5;
            int d4  = (idx & 31) << 2;
            *(float4*)&KVs[r * 132 + d4] =
                *(const float4*)&Kb[(size_t)(k0 + r) * KCOLS + kvoff + d4];
        }
        __syncthreads();

        // ---- scores: acc[4][4] = Qtile . Ktile^T ----
        float acc[4][4];
#pragma unroll
        for (int r = 0; r < 4; r++)
#pragma unroll
            for (int c = 0; c < 4; c++) acc[r][c] = 0.0f;

#pragma unroll 2
        for (int d0 = 0; d0 < 128; d0 += 4) {
            float4 qa[4], kb[4];
#pragma unroll
            for (int r = 0; r < 4; r++)
                qa[r] = *(const float4*)&Qs[(ty * 4 + r) * 132 + d0];
#pragma unroll
            for (int c = 0; c < 4; c++)
                kb[c] = *(const float4*)&KVs[(tx * 4 + c) * 132 + d0];
#pragma unroll
            for (int r = 0; r < 4; r++)
#pragma unroll
                for (int c = 0; c < 4; c++)
                    acc[r][c] += qa[r].x * kb[c].x + qa[r].y * kb[c].y +
                                 qa[r].z * kb[c].z + qa[r].w * kb[c].w;
        }

        // ---- online softmax (per q-row, across the 16 tx lanes) ----
        const bool diag = (kt == qt);
#pragma unroll
        for (int r = 0; r < 4; r++) {
            int qrel = ty * 4 + r;
            float pv[4];
            float tmax = -INFINITY;
#pragma unroll
            for (int c = 0; c < 4; c++) {
                float s = acc[r][c] * scale;
                if (diag && (tx * 4 + c) > qrel) s = -1e30f;
                acc[r][c] = s;
                tmax = fmaxf(tmax, s);
            }
#pragma unroll
            for (int off = 1; off < 16; off <<= 1)
                tmax = fmaxf(tmax, __shfl_xor_sync(0xffffffffu, tmax, off));

            float mnew  = fmaxf(m_r[r], tmax);
            float alpha = __expf(m_r[r] - mnew);
            m_r[r] = mnew;

            float rs = 0.0f;
#pragma unroll
            for (int c = 0; c < 4; c++) {
                pv[c] = __expf(acc[r][c] - mnew);
                rs += pv[c];
            }
#pragma unroll
            for (int off = 1; off < 16; off <<= 1)
                rs += __shfl_xor_sync(0xffffffffu, rs, off);

            l_r[r] = l_r[r] * alpha + rs;
#pragma unroll
            for (int j = 0; j < 8; j++) o_r[r][j] *= alpha;

            *(float4*)&Ps[qrel * 72 + tx * 4] =
                make_float4(pv[0], pv[1], pv[2], pv[3]);
        }
        __syncthreads();   // Ps visible; KVs reads done

        // ---- load V tile (overwrites K tile) ----
#pragma unroll
        for (int i = 0; i < 8; i++) {
            int idx = t + i * 256;
            int r   = idx >> 5;
            int d4  = (idx & 31) << 2;
            *(float4*)&KVs[r * 132 + d4] =
                *(const float4*)&Vb[(size_t)(k0 + r) * KCOLS + kvoff + d4];
        }
        __syncthreads();

        // ---- O += P . V ----
#pragma unroll 2
        for (int k = 0; k < 64; k++) {
            float4 v0 = *(const float4*)&KVs[k * 132 + tx * 4];
            float4 v1 = *(const float4*)&KVs[k * 132 + 64 + tx * 4];
#pragma unroll
            for (int r = 0; r < 4; r++) {
                float p = Ps[(ty * 4 + r) * 72 + k];
                o_r[r][0] += p * v0.x; o_r[r][1] += p * v0.y;
                o_r[r][2] += p * v0.z; o_r[r][3] += p * v0.w;
                o_r[r][4] += p * v1.x; o_r[r][5] += p * v1.y;
                o_r[r][6] += p * v1.z; o_r[r][7] += p * v1.w;
            }
        }
        __syncthreads();   // before next iteration overwrites KVs / Ps
    }

    // ---- epilogue: normalize and write [S, HQ*D] ----
#pragma unroll
    for (int r = 0; r < 4; r++) {
        float inv = 1.0f / l_r[r];
        size_t base = (size_t)(q0 + ty * 4 + r) * QCOLS + h * D_HEAD;
        *(float4*)&O[base + tx * 4] =
            make_float4(o_r[r][0] * inv, o_r[r][1] * inv,
                        o_r[r][2] * inv, o_r[r][3] * inv);
        *(float4*)&O[base + 64 + tx * 4] =
            make_float4(o_r[r][4] * inv, o_r[r][5] * inv,
                        o_r[r][6] * inv, o_r[r][7] * inv);
    }
}

// ============================================================================
// kernel_launch
// inputs: 0 hidden_states f32 [1,3072,2048], 1 attention_mask (unused, causal),
//         2 position_ids i32 [1,3072], 3 Wq [2048,2048], 4 Wk [256,2048],
//         5 Wv [256,2048], 6 Wo [2048,2048]
// ============================================================================
extern "C" void kernel_launch(void* const* d_in, const int* in_sizes, int n_in,
                              void* d_out, int out_size) {
    (void)in_sizes; (void)n_in; (void)out_size;
    const float* hidden = (const float*)d_in[0];
    const int*   pos    = (const int*)d_in[2];
    const float* Wq     = (const float*)d_in[3];
    const float* Wk     = (const float*)d_in[4];
    const float* Wv     = (const float*)d_in[5];
    const float* Wo     = (const float*)d_in[6];
    float* out = (float*)d_out;

    // Device-global scratch addresses. cudaGetSymbolAddress is a pure lookup
    // (no allocation, not a stream operation) — legal during graph capture.
    float *Qp, *Kp, *Vp, *Ap;
    cudaGetSymbolAddress((void**)&Qp, g_Q);
    cudaGetSymbolAddress((void**)&Kp, g_K);
    cudaGetSymbolAddress((void**)&Vp, g_V);
    cudaGetSymbolAddress((void**)&Ap, g_A);

    // Idempotent attribute set (no static guards allowed in kernel_launch).
    cudaFuncSetAttribute(flash_kernel,
                         cudaFuncAttributeMaxDynamicSharedMemorySize, SMEM_FLASH);

    dim3 blk(256);
    // projections
    sgemm_nt<<<dim3(QCOLS / 128, S_LEN / 128), blk>>>(hidden, Wq, Qp, S_LEN, QCOLS, HIDDEN);
    sgemm_nt<<<dim3(KCOLS / 128, S_LEN / 128), blk>>>(hidden, Wk, Kp, S_LEN, KCOLS, HIDDEN);
    sgemm_nt<<<dim3(KCOLS / 128, S_LEN / 128), blk>>>(hidden, Wv, Vp, S_LEN, KCOLS, HIDDEN);
    // RoPE on Q and K
    rope_kernel<<<(S_LEN * HQ * 64 + 255) / 256, 256>>>(Qp, pos, HQ, S_LEN * HQ * 64);
    rope_kernel<<<(S_LEN * HK * 64 + 255) / 256, 256>>>(Kp, pos, HK, S_LEN * HK * 64);
    // causal flash attention (48 q-tiles x 16 heads)
    flash_kernel<<<dim3(S_LEN / 64, HQ), blk, SMEM_FLASH>>>(Qp, Kp, Vp, Ap);
    // output projection
    sgemm_nt<<<dim3(QCOLS / 128, S_LEN / 128), blk>>>(Ap, Wo, out, S_LEN, QCOLS, HIDDEN);
}

// round 6
// speedup vs baseline: 1.3444x; 1.3444x over previous
#include <cuda_runtime.h>
#include <math.h>
#include <stdint.h>

#define S_LEN   3072
#define HIDDEN  2048
#define HQ      16
#define HK      2
#define D_HEAD  128
#define QCOLS   (HQ * D_HEAD)   // 2048
#define KCOLS   (HK * D_HEAD)   // 256
#define NSHARED 8

// ---------------- scratch (device globals: no allocations allowed) ----------
__device__ float g_Q[S_LEN * QCOLS];   // 24 MB
__device__ float g_K[S_LEN * KCOLS];   //  3 MB
__device__ float g_V[S_LEN * KCOLS];   //  3 MB
__device__ float g_A[S_LEN * QCOLS];   // 24 MB (attention output, pre-Wo)

// ============================================================================
// TF32 tensor-core GEMM: C[M,N] = A[M,K] * B[N,K]^T   (row-major fp32 in/out)
// BM=BN=128, BK=32, 256 threads (8 warps, 2x4), warp tile 64x32.
// mma.sync.aligned.m16n8k8.row.col.f32.tf32.tf32.f32
// Smem holds tiles in FRAGMENT-PERMUTED order so each fragment load is a
// single LDS.128 (A) / LDS.64 (B), conflict-free.
// Requires M%128==0, N%128==0, K%32==0 (true for all calls here).
// ============================================================================
__device__ __forceinline__ uint32_t f2tf32(float f) {
    uint32_t u;
    asm("cvt.rna.tf32.f32 %0, %1;" : "=r"(u) : "f"(f));
    return u;
}

__device__ __forceinline__ void mma_tf32(float& d0, float& d1, float& d2, float& d3,
                                         uint32_t a0, uint32_t a1, uint32_t a2, uint32_t a3,
                                         uint32_t b0, uint32_t b1) {
    asm volatile(
        "mma.sync.aligned.m16n8k8.row.col.f32.tf32.tf32.f32 "
        "{%0,%1,%2,%3}, {%4,%5,%6,%7}, {%8,%9}, {%0,%1,%2,%3};\n"
        : "+f"(d0), "+f"(d1), "+f"(d2), "+f"(d3)
        : "r"(a0), "r"(a1), "r"(a2), "r"(a3), "r"(b0), "r"(b1));
}

__global__ __launch_bounds__(256, 1)
void tf32_gemm_nt(const float* __restrict__ A, const float* __restrict__ B,
                  float* __restrict__ C, int M, int N, int K) {
    // As: [kstep(4)][msub(8)][lane(32)][4]   = 4096 u32 = 16 KB
    // Bs: [kstep(4)][nsub(16)][lane(32)][2]  = 4096 u32 = 16 KB
    __shared__ uint32_t As[4096];
    __shared__ uint32_t Bs[4096];

    const int t    = threadIdx.x;
    const int warp = t >> 5;
    const int lane = t & 31;
    const int wm   = (warp >> 2) * 64;    // warp m origin in block (0 or 64)
    const int wn   = (warp & 3) * 32;     // warp n origin in block
    const int bm   = blockIdx.y * 128;
    const int bn   = blockIdx.x * 128;

    // ---- per-thread global-load geometry (4 float4 each for A and B) ----
    // float4 id = t + i*256 ; row = id>>3 ; cpos = id&7 ; col = cpos*4
    int rowA[4], aBase[4];
    int rowB[4], bBase[4];
#pragma unroll
    for (int i = 0; i < 4; i++) {
        int id   = t + i * 256;
        int row  = id >> 3;
        int cpos = id & 7;
        int kstep = cpos >> 1;
        // A scatter: msub=row>>4, r8=(row>>3)&1, rr=row&7, c4=cpos&1
        {
            int msub = row >> 4, r8 = (row >> 3) & 1, rr = row & 7, c4 = cpos & 1;
            rowA[i]  = row;
            aBase[i] = ((kstep * 8 + msub) * 32 + rr * 4) * 4 + (r8 + 2 * c4);
        }
        // B scatter: nsub=row>>3, nn=row&7, k4=cpos&1
        {
            int nsub = row >> 3, nn = row & 7, k4 = cpos & 1;
            rowB[i]  = row;
            bBase[i] = ((kstep * 16 + nsub) * 32 + nn * 4) * 2 + k4;
        }
    }

    const float* aPtr[4];
    const float* bPtr[4];
#pragma unroll
    for (int i = 0; i < 4; i++) {
        int id = t + i * 256;
        int colg = (id & 7) * 4;
        aPtr[i] = A + (size_t)(bm + rowA[i]) * K + colg;
        bPtr[i] = B + (size_t)(bn + rowB[i]) * K + colg;
    }

    float acc[4][4][4];
#pragma unroll
    for (int m = 0; m < 4; m++)
#pragma unroll
        for (int n = 0; n < 4; n++)
#pragma unroll
            for (int r = 0; r < 4; r++) acc[m][n][r] = 0.0f;

    // ---- prefetch first tile ----
    float4 pa[4], pb[4];
#pragma unroll
    for (int i = 0; i < 4; i++) {
        pa[i] = *(const float4*)aPtr[i];
        pb[i] = *(const float4*)bPtr[i];
    }

    const int wm4 = wm >> 4;   // warp msub origin (0 or 4)
    const int wn8 = wn >> 3;   // warp nsub origin (0,4,8,12)

    for (int k0 = 0; k0 < K; k0 += 32) {
        // ---- store prefetched tile (tf32-convert on the way in) ----
#pragma unroll
        for (int i = 0; i < 4; i++) {
            As[aBase[i] + 0]  = f2tf32(pa[i].x);
            As[aBase[i] + 4]  = f2tf32(pa[i].y);
            As[aBase[i] + 8]  = f2tf32(pa[i].z);
            As[aBase[i] + 12] = f2tf32(pa[i].w);
            Bs[bBase[i] + 0]  = f2tf32(pb[i].x);
            Bs[bBase[i] + 2]  = f2tf32(pb[i].y);
            Bs[bBase[i] + 4]  = f2tf32(pb[i].z);
            Bs[bBase[i] + 6]  = f2tf32(pb[i].w);
        }
        __syncthreads();

        // ---- prefetch next tile while computing this one ----
        if (k0 + 32 < K) {
#pragma unroll
            for (int i = 0; i < 4; i++) {
                aPtr[i] += 32; bPtr[i] += 32;
                pa[i] = *(const float4*)aPtr[i];
                pb[i] = *(const float4*)bPtr[i];
            }
        }

        // ---- compute: 4 ksteps x (4 msub x 4 nsub) mma ----
#pragma unroll
        for (int ks = 0; ks < 4; ks++) {
            uint4 af[4];
            uint2 bf[4];
#pragma unroll
            for (int m = 0; m < 4; m++)
                af[m] = *(const uint4*)&As[((ks * 8 + wm4 + m) * 32 + lane) * 4];
#pragma unroll
            for (int n = 0; n < 4; n++)
                bf[n] = *(const uint2*)&Bs[((ks * 16 + wn8 + n) * 32 + lane) * 2];
#pragma unroll
            for (int m = 0; m < 4; m++)
#pragma unroll
                for (int n = 0; n < 4; n++)
                    mma_tf32(acc[m][n][0], acc[m][n][1], acc[m][n][2], acc[m][n][3],
                             af[m].x, af[m].y, af[m].z, af[m].w,
                             bf[n].x, bf[n].y);
        }
        __syncthreads();
    }

    // ---- epilogue ----
    const int lr = lane >> 2;            // row within 16-row subtile
    const int lc = (lane & 3) * 2;       // col within 8-col subtile
#pragma unroll
    for (int m = 0; m < 4; m++) {
#pragma unroll
        for (int n = 0; n < 4; n++) {
            int r0 = bm + wm + m * 16 + lr;
            int c0 = bn + wn + n * 8 + lc;
            *(float2*)&C[(size_t)r0 * N + c0] =
                make_float2(acc[m][n][0], acc[m][n][1]);
            *(float2*)&C[(size_t)(r0 + 8) * N + c0] =
                make_float2(acc[m][n][2], acc[m][n][3]);
        }
    }
}

// ============================================================================
// RoPE in-place. One thread per rotation pair (s, head, fi<64).
// ============================================================================
__global__ void rope_kernel(float* __restrict__ x, const int* __restrict__ pos,
                            int nheads, int total) {
    int idx = blockIdx.x * blockDim.x + threadIdx.x;
    if (idx >= total) return;
    int fi = idx & 63;
    int h  = (idx >> 6) % nheads;
    int s  = idx / (nheads * 64);

    float p    = (float)pos[s];
    float invf = powf(10000.0f, -((float)fi) / 64.0f);
    float sn, cs;
    sincosf(p * invf, &sn, &cs);   // accurate range reduction (angle up to ~3071)

    size_t base = (size_t)s * (nheads * D_HEAD) + h * D_HEAD + fi;
    float x1 = x[base];
    float x2 = x[base + 64];
    x[base]      = x1 * cs - x2 * sn;
    x[base + 64] = x2 * cs + x1 * sn;
}

// ============================================================================
// Flash attention, fp32, causal. Block = (q-tile of 64, head). 256 threads.
// GQA mapping: reference uses jnp.tile, so q-head h -> kv-head (h & 1).
// ============================================================================
#define SMEM_FLASH ((2 * 64 * 132 + 64 * 72) * 4)   // 86016 bytes

__global__ __launch_bounds__(256, 2)
void flash_kernel(const float* __restrict__ Q, const float* __restrict__ Kb,
                  const float* __restrict__ Vb, float* __restrict__ O) {
    extern __shared__ float sm[];
    float* Qs  = sm;                  // [64][132]
    float* KVs = sm + 64 * 132;       // [64][132]
    float* Ps  = sm + 2 * 64 * 132;   // [64][72]

    const int t  = threadIdx.x;
    const int tx = t & 15;
    const int ty = t >> 4;
    const int qt = gridDim.x - 1 - blockIdx.x;   // longest blocks launch first
    const int h  = blockIdx.y;
    const int q0 = qt * 64;
    const int kvoff = (h & 1) * D_HEAD;          // GQA: kv head = h % HK (tile!)

#pragma unroll
    for (int i = 0; i < 8; i++) {
        int idx = t + i * 256;
        int r   = idx >> 5;
        int d4  = (idx & 31) << 2;
        *(float4*)&Qs[r * 132 + d4] =
            *(const float4*)&Q[(size_t)(q0 + r) * QCOLS + h * D_HEAD + d4];
    }

    float m_r[4], l_r[4], o_r[4][8];
#pragma unroll
    for (int r = 0; r < 4; r++) {
        m_r[r] = -INFINITY;
        l_r[r] = 0.0f;
#pragma unroll
        for (int j = 0; j < 8; j++) o_r[r][j] = 0.0f;
    }

    const float scale = 0.08838834764831845f;   // 1/sqrt(128)

    for (int kt = 0; kt <= qt; kt++) {
        const int k0 = kt * 64;

#pragma unroll
        for (int i = 0; i < 8; i++) {
            int idx = t + i * 256;
            int r   = idx >> 5;
            int d4  = (idx & 31) << 2;
            *(float4*)&KVs[r * 132 + d4] =
                *(const float4*)&Kb[(size_t)(k0 + r) * KCOLS + kvoff + d4];
        }
        __syncthreads();

        float acc[4][4];
#pragma unroll
        for (int r = 0; r < 4; r++)
#pragma unroll
            for (int c = 0; c < 4; c++) acc[r][c] = 0.0f;

#pragma unroll 2
        for (int d0 = 0; d0 < 128; d0 += 4) {
            float4 qa[4], kb[4];
#pragma unroll
            for (int r = 0; r < 4; r++)
                qa[r] = *(const float4*)&Qs[(ty * 4 + r) * 132 + d0];
#pragma unroll
            for (int c = 0; c < 4; c++)
                kb[c] = *(const float4*)&KVs[(tx * 4 + c) * 132 + d0];
#pragma unroll
            for (int r = 0; r < 4; r++)
#pragma unroll
                for (int c = 0; c < 4; c++)
                    acc[r][c] += qa[r].x * kb[c].x + qa[r].y * kb[c].y +
                                 qa[r].z * kb[c].z + qa[r].w * kb[c].w;
        }

        const bool diag = (kt == qt);
#pragma unroll
        for (int r = 0; r < 4; r++) {
            int qrel = ty * 4 + r;
            float pv[4];
            float tmax = -INFINITY;
#pragma unroll
            for (int c = 0; c < 4; c++) {
                float s = acc[r][c] * scale;
                if (diag && (tx * 4 + c) > qrel) s = -1e30f;
                acc[r][c] = s;
                tmax = fmaxf(tmax, s);
            }
#pragma unroll
            for (int off = 1; off < 16; off <<= 1)
                tmax = fmaxf(tmax, __shfl_xor_sync(0xffffffffu, tmax, off));

            float mnew  = fmaxf(m_r[r], tmax);
            float alpha = __expf(m_r[r] - mnew);
            m_r[r] = mnew;

            float rs = 0.0f;
#pragma unroll
            for (int c = 0; c < 4; c++) {
                pv[c] = __expf(acc[r][c] - mnew);
                rs += pv[c];
            }
#pragma unroll
            for (int off = 1; off < 16; off <<= 1)
                rs += __shfl_xor_sync(0xffffffffu, rs, off);

            l_r[r] = l_r[r] * alpha + rs;
#pragma unroll
            for (int j = 0; j < 8; j++) o_r[r][j] *= alpha;

            *(float4*)&Ps[qrel * 72 + tx * 4] =
                make_float4(pv[0], pv[1], pv[2], pv[3]);
        }
        __syncthreads();   // Ps visible; KVs reads done

#pragma unroll
        for (int i = 0; i < 8; i++) {
            int idx = t + i * 256;
            int r   = idx >> 5;
            int d4  = (idx & 31) << 2;
            *(float4*)&KVs[r * 132 + d4] =
                *(const float4*)&Vb[(size_t)(k0 + r) * KCOLS + kvoff + d4];
        }
        __syncthreads();

#pragma unroll 2
        for (int k = 0; k < 64; k++) {
            float4 v0 = *(const float4*)&KVs[k * 132 + tx * 4];
            float4 v1 = *(const float4*)&KVs[k * 132 + 64 + tx * 4];
#pragma unroll
            for (int r = 0; r < 4; r++) {
                float p = Ps[(ty * 4 + r) * 72 + k];
                o_r[r][0] += p * v0.x; o_r[r][1] += p * v0.y;
                o_r[r][2] += p * v0.z; o_r[r][3] += p * v0.w;
                o_r[r][4] += p * v1.x; o_r[r][5] += p * v1.y;
                o_r[r][6] += p * v1.z; o_r[r][7] += p * v1.w;
            }
        }
        __syncthreads();   // before next iteration overwrites KVs / Ps
    }

#pragma unroll
    for (int r = 0; r < 4; r++) {
        float inv = 1.0f / l_r[r];
        size_t base = (size_t)(q0 + ty * 4 + r) * QCOLS + h * D_HEAD;
        *(float4*)&O[base + tx * 4] =
            make_float4(o_r[r][0] * inv, o_r[r][1] * inv,
                        o_r[r][2] * inv, o_r[r][3] * inv);
        *(float4*)&O[base + 64 + tx * 4] =
            make_float4(o_r[r][4] * inv, o_r[r][5] * inv,
                        o_r[r][6] * inv, o_r[r][7] * inv);
    }
}

// ============================================================================
// kernel_launch
// inputs: 0 hidden_states f32 [1,3072,2048], 1 attention_mask (unused, causal),
//         2 position_ids i32 [1,3072], 3 Wq [2048,2048], 4 Wk [256,2048],
//         5 Wv [256,2048], 6 Wo [2048,2048]
// ============================================================================
extern "C" void kernel_launch(void* const* d_in, const int* in_sizes, int n_in,
                              void* d_out, int out_size) {
    (void)in_sizes; (void)n_in; (void)out_size;
    const float* hidden = (const float*)d_in[0];
    const int*   pos    = (const int*)d_in[2];
    const float* Wq     = (const float*)d_in[3];
    const float* Wk     = (const float*)d_in[4];
    const float* Wv     = (const float*)d_in[5];
    const float* Wo     = (const float*)d_in[6];
    float* out = (float*)d_out;

    float *Qp, *Kp, *Vp, *Ap;
    cudaGetSymbolAddress((void**)&Qp, g_Q);
    cudaGetSymbolAddress((void**)&Kp, g_K);
    cudaGetSymbolAddress((void**)&Vp, g_V);
    cudaGetSymbolAddress((void**)&Ap, g_A);

    cudaFuncSetAttribute(flash_kernel,
                         cudaFuncAttributeMaxDynamicSharedMemorySize, SMEM_FLASH);

    dim3 blk(256);
    // projections (TF32 tensor cores)
    tf32_gemm_nt<<<dim3(QCOLS / 128, S_LEN / 128), blk>>>(hidden, Wq, Qp, S_LEN, QCOLS, HIDDEN);
    tf32_gemm_nt<<<dim3(KCOLS / 128, S_LEN / 128), blk>>>(hidden, Wk, Kp, S_LEN, KCOLS, HIDDEN);
    tf32_gemm_nt<<<dim3(KCOLS / 128, S_LEN / 128), blk>>>(hidden, Wv, Vp, S_LEN, KCOLS, HIDDEN);
    // RoPE on Q and K
    rope_kernel<<<(S_LEN * HQ * 64 + 255) / 256, 256>>>(Qp, pos, HQ, S_LEN * HQ * 64);
    rope_kernel<<<(S_LEN * HK * 64 + 255) / 256, 256>>>(Kp, pos, HK, S_LEN * HK * 64);
    // causal flash attention (48 q-tiles x 16 heads), fp32
    flash_kernel<<<dim3(S_LEN / 64, HQ), blk, SMEM_FLASH>>>(Qp, Kp, Vp, Ap);
    // output projection (TF32)
    tf32_gemm_nt<<<dim3(QCOLS / 128, S_LEN / 128), blk>>>(Ap, Wo, out, S_LEN, QCOLS, HIDDEN);
}

// round 8
// speedup vs baseline: 2.3800x; 1.7704x over previous
#include <cuda_runtime.h>
#include <math.h>
#include <stdint.h>

#define S_LEN   3072
#define HIDDEN  2048
#define HQ      16
#define HK      2
#define D_HEAD  128
#define QCOLS   (HQ * D_HEAD)   // 2048
#define KCOLS   (HK * D_HEAD)   // 256

// ---------------- scratch (device globals: no allocations allowed) ----------
__device__ float g_Q[S_LEN * QCOLS];   // 24 MB
__device__ float g_K[S_LEN * KCOLS];   //  3 MB
__device__ float g_V[S_LEN * KCOLS];   //  3 MB
__device__ float g_A[S_LEN * QCOLS];   // 24 MB (attention output, pre-Wo)

// ============================================================================
// Common TF32 helpers
// ============================================================================
__device__ __forceinline__ uint32_t f2tf32(float f) {
    uint32_t u;
    asm("cvt.rna.tf32.f32 %0, %1;" : "=r"(u) : "f"(f));
    return u;
}

__device__ __forceinline__ void mma_tf32(float& d0, float& d1, float& d2, float& d3,
                                         uint32_t a0, uint32_t a1, uint32_t a2, uint32_t a3,
                                         uint32_t b0, uint32_t b1) {
    asm volatile(
        "mma.sync.aligned.m16n8k8.row.col.f32.tf32.tf32.f32 "
        "{%0,%1,%2,%3}, {%4,%5,%6,%7}, {%8,%9}, {%0,%1,%2,%3};\n"
        : "+f"(d0), "+f"(d1), "+f"(d2), "+f"(d3)
        : "r"(a0), "r"(a1), "r"(a2), "r"(a3), "r"(b0), "r"(b1));
}

// ============================================================================
// TF32 tensor-core GEMM: C[M,N] = A[M,K] * B[N,K]^T   (row-major fp32 in/out)
// BM=BN=128, BK=32, 256 threads (8 warps, 2x4), warp tile 64x32.
// Fragment-permuted smem: every fragment load is one LDS.128/LDS.64.
// ============================================================================
__global__ __launch_bounds__(256, 1)
void tf32_gemm_nt(const float* __restrict__ A, const float* __restrict__ B,
                  float* __restrict__ C, int M, int N, int K) {
    __shared__ uint32_t As[4096];
    __shared__ uint32_t Bs[4096];

    const int t    = threadIdx.x;
    const int warp = t >> 5;
    const int lane = t & 31;
    const int wm   = (warp >> 2) * 64;
    const int wn   = (warp & 3) * 32;
    const int bm   = blockIdx.y * 128;
    const int bn   = blockIdx.x * 128;

    int rowA[4], aBase[4];
    int rowB[4], bBase[4];
#pragma unroll
    for (int i = 0; i < 4; i++) {
        int id   = t + i * 256;
        int row  = id >> 3;
        int cpos = id & 7;
        int kstep = cpos >> 1;
        {
            int msub = row >> 4, r8 = (row >> 3) & 1, rr = row & 7, c4 = cpos & 1;
            rowA[i]  = row;
            aBase[i] = ((kstep * 8 + msub) * 32 + rr * 4) * 4 + (r8 + 2 * c4);
        }
        {
            int nsub = row >> 3, nn = row & 7, k4 = cpos & 1;
            rowB[i]  = row;
            bBase[i] = ((kstep * 16 + nsub) * 32 + nn * 4) * 2 + k4;
        }
    }

    const float* aPtr[4];
    const float* bPtr[4];
#pragma unroll
    for (int i = 0; i < 4; i++) {
        int id = t + i * 256;
        int colg = (id & 7) * 4;
        aPtr[i] = A + (size_t)(bm + rowA[i]) * K + colg;
        bPtr[i] = B + (size_t)(bn + rowB[i]) * K + colg;
    }

    float acc[4][4][4];
#pragma unroll
    for (int m = 0; m < 4; m++)
#pragma unroll
        for (int n = 0; n < 4; n++)
#pragma unroll
            for (int r = 0; r < 4; r++) acc[m][n][r] = 0.0f;

    float4 pa[4], pb[4];
#pragma unroll
    for (int i = 0; i < 4; i++) {
        pa[i] = *(const float4*)aPtr[i];
        pb[i] = *(const float4*)bPtr[i];
    }

    const int wm4 = wm >> 4;
    const int wn8 = wn >> 3;

    for (int k0 = 0; k0 < K; k0 += 32) {
#pragma unroll
        for (int i = 0; i < 4; i++) {
            As[aBase[i] + 0]  = f2tf32(pa[i].x);
            As[aBase[i] + 4]  = f2tf32(pa[i].y);
            As[aBase[i] + 8]  = f2tf32(pa[i].z);
            As[aBase[i] + 12] = f2tf32(pa[i].w);
            Bs[bBase[i] + 0]  = f2tf32(pb[i].x);
            Bs[bBase[i] + 2]  = f2tf32(pb[i].y);
            Bs[bBase[i] + 4]  = f2tf32(pb[i].z);
            Bs[bBase[i] + 6]  = f2tf32(pb[i].w);
        }
        __syncthreads();

        if (k0 + 32 < K) {
#pragma unroll
            for (int i = 0; i < 4; i++) {
                aPtr[i] += 32; bPtr[i] += 32;
                pa[i] = *(const float4*)aPtr[i];
                pb[i] = *(const float4*)bPtr[i];
            }
        }

#pragma unroll
        for (int ks = 0; ks < 4; ks++) {
            uint4 af[4];
            uint2 bf[4];
#pragma unroll
            for (int m = 0; m < 4; m++)
                af[m] = *(const uint4*)&As[((ks * 8 + wm4 + m) * 32 + lane) * 4];
#pragma unroll
            for (int n = 0; n < 4; n++)
                bf[n] = *(const uint2*)&Bs[((ks * 16 + wn8 + n) * 32 + lane) * 2];
#pragma unroll
            for (int m = 0; m < 4; m++)
#pragma unroll
                for (int n = 0; n < 4; n++)
                    mma_tf32(acc[m][n][0], acc[m][n][1], acc[m][n][2], acc[m][n][3],
                             af[m].x, af[m].y, af[m].z, af[m].w,
                             bf[n].x, bf[n].y);
        }
        __syncthreads();
    }

    const int lr = lane >> 2;
    const int lc = (lane & 3) * 2;
#pragma unroll
    for (int m = 0; m < 4; m++) {
#pragma unroll
        for (int n = 0; n < 4; n++) {
            int r0 = bm + wm + m * 16 + lr;
            int c0 = bn + wn + n * 8 + lc;
            *(float2*)&C[(size_t)r0 * N + c0] =
                make_float2(acc[m][n][0], acc[m][n][1]);
            *(float2*)&C[(size_t)(r0 + 8) * N + c0] =
                make_float2(acc[m][n][2], acc[m][n][3]);
        }
    }
}

// ============================================================================
// RoPE in-place.
// ============================================================================
__global__ void rope_kernel(float* __restrict__ x, const int* __restrict__ pos,
                            int nheads, int total) {
    int idx = blockIdx.x * blockDim.x + threadIdx.x;
    if (idx >= total) return;
    int fi = idx & 63;
    int h  = (idx >> 6) % nheads;
    int s  = idx / (nheads * 64);

    float p    = (float)pos[s];
    float invf = powf(10000.0f, -((float)fi) / 64.0f);
    float sn, cs;
    sincosf(p * invf, &sn, &cs);

    size_t base = (size_t)s * (nheads * D_HEAD) + h * D_HEAD + fi;
    float x1 = x[base];
    float x2 = x[base + 64];
    x[base]      = x1 * cs - x2 * sn;
    x[base + 64] = x2 * cs + x1 * sn;
}

// ============================================================================
// TF32 tensor-core causal flash attention.
// Block = 256 threads (8 warps) x (q-tile 128, head). Warp w owns q-rows
// [w*16, w*16+16). K/V tiles of 64 keys. GQA: q-head h -> kv-head (h & 1).
//
// Smem (u32 offsets):
//   Qs [16 ks][8 msub][32 lane][4]   = 16384  (A-op fragments, pre-scaled)
//   Ks [16 ks][8 nsub][32 lane][2]   =  8192  (B-op: n=key, k=d)
//   Vs [ 8 ks][16 nsub][32 lane][2]  =  8192  (B-op: n=d,   k=key)
//   Ps [8 warp][8 ks][32 lane][4]    =  8192  (A-op: P, warp-private)
// Total 40960 u32 = 160 KB.
// ============================================================================
#define SMEM_FA (40960 * 4)

__global__ __launch_bounds__(256, 1)
void flash_tf32(const float* __restrict__ Q, const float* __restrict__ Kb,
                const float* __restrict__ Vb, float* __restrict__ O) {
    extern __shared__ uint32_t sm[];
    uint32_t* Qs = sm;            // 16384
    uint32_t* Ks = sm + 16384;    //  8192
    uint32_t* Vs = sm + 24576;    //  8192
    uint32_t* Ps = sm + 32768;    //  8192

    const int t    = threadIdx.x;
    const int w    = t >> 5;
    const int lane = t & 31;
    const int qt   = gridDim.x - 1 - blockIdx.x;   // longest blocks first
    const int h    = blockIdx.y;
    const int q0   = qt * 128;
    const int kvoff = (h & 1) * D_HEAD;
    const float SCALE = 0.08838834764831845f;      // 1/sqrt(128)

    // ---- load Q tile (128x128) into A-fragment smem, pre-scaled ----
#pragma unroll
    for (int i = 0; i < 16; i++) {
        int id  = t + i * 256;
        int row = id >> 5;
        int cp  = id & 31;
        float4 qv = *(const float4*)&Q[(size_t)(q0 + row) * QCOLS + h * D_HEAD + cp * 4];
        int msub = row >> 4, m8 = (row >> 3) & 1, rr = row & 7;
        int ks = cp >> 1, c4 = cp & 1;
        int base = ((ks * 8 + msub) * 32 + rr * 4) * 4 + (m8 + 2 * c4);
        Qs[base + 0]  = f2tf32(qv.x * SCALE);
        Qs[base + 4]  = f2tf32(qv.y * SCALE);
        Qs[base + 8]  = f2tf32(qv.z * SCALE);
        Qs[base + 12] = f2tf32(qv.w * SCALE);
    }

    // ---- persistent state ----
    float m_[2] = {-INFINITY, -INFINITY};
    float l_[2] = {0.0f, 0.0f};
    float o_[16][4];
#pragma unroll
    for (int n = 0; n < 16; n++)
#pragma unroll
        for (int r = 0; r < 4; r++) o_[n][r] = 0.0f;

    const int nkt = qt * 2 + 2;   // k-tiles (64 keys each)
    const int r   = lane >> 2;
    const int c2  = (lane & 3) * 2;
    const int rg0 = q0 + w * 16 + r;
    const int rg1 = rg0 + 8;

    // ---- prefetch tile 0 ----
    float4 kf[8], vf[8];
#pragma unroll
    for (int i = 0; i < 8; i++) {
        int id = t + i * 256;
        int row = id >> 5, cp = id & 31;
        kf[i] = *(const float4*)&Kb[(size_t)row * KCOLS + kvoff + cp * 4];
        vf[i] = *(const float4*)&Vb[(size_t)row * KCOLS + kvoff + cp * 4];
    }

    for (int kt = 0; kt < nkt; kt++) {
        const int k0 = kt * 64;

        // ---- scatter prefetched K,V into fragment smem ----
#pragma unroll
        for (int i = 0; i < 8; i++) {
            int id = t + i * 256;
            int row = id >> 5, cp = id & 31;
            int ks = cp >> 1, k4 = cp & 1;
            // K: B-op (n=key=row, k=d)
            int kb = ((ks * 8 + (row >> 3)) * 32 + (row & 7) * 4) * 2 + k4;
            Ks[kb + 0] = f2tf32(kf[i].x);
            Ks[kb + 2] = f2tf32(kf[i].y);
            Ks[kb + 4] = f2tf32(kf[i].z);
            Ks[kb + 6] = f2tf32(kf[i].w);
            // V: B-op (n=d, k=key=row)
            int vks = row >> 3, vk4 = (row & 7) >> 2, vq = row & 3;
            int nsub = cp >> 1, nnb = (cp & 1) * 4;
            int vb = ((vks * 16 + nsub) * 32 + nnb * 4 + vq) * 2 + vk4;
            Vs[vb + 0]  = f2tf32(vf[i].x);
            Vs[vb + 8]  = f2tf32(vf[i].y);
            Vs[vb + 16] = f2tf32(vf[i].z);
            Vs[vb + 24] = f2tf32(vf[i].w);
        }
        __syncthreads();

        // ---- prefetch next K/V tile ----
        if (kt + 1 < nkt) {
            int k0n = (kt + 1) * 64;
#pragma unroll
            for (int i = 0; i < 8; i++) {
                int id = t + i * 256;
                int row = id >> 5, cp = id & 31;
                kf[i] = *(const float4*)&Kb[(size_t)(k0n + row) * KCOLS + kvoff + cp * 4];
                vf[i] = *(const float4*)&Vb[(size_t)(k0n + row) * KCOLS + kvoff + cp * 4];
            }
        }

        // ---- scores: S[16x64] per warp ----
        float acc[8][4];
#pragma unroll
        for (int n = 0; n < 8; n++)
#pragma unroll
            for (int x = 0; x < 4; x++) acc[n][x] = 0.0f;

#pragma unroll
        for (int ks = 0; ks < 16; ks++) {
            uint4 a = *(const uint4*)&Qs[((ks * 8 + w) * 32 + lane) * 4];
#pragma unroll
            for (int nt = 0; nt < 8; nt++) {
                uint2 b = *(const uint2*)&Ks[((ks * 8 + nt) * 32 + lane) * 2];
                mma_tf32(acc[nt][0], acc[nt][1], acc[nt][2], acc[nt][3],
                         a.x, a.y, a.z, a.w, b.x, b.y);
            }
        }

        // ---- causal mask (only last two k-tiles touch the diagonal) ----
        if (kt >= nkt - 2) {
#pragma unroll
            for (int nt = 0; nt < 8; nt++) {
                int cg = k0 + nt * 8 + c2;
                if (cg > rg0)     acc[nt][0] = -1e30f;
                if (cg + 1 > rg0) acc[nt][1] = -1e30f;
                if (cg > rg1)     acc[nt][2] = -1e30f;
                if (cg + 1 > rg1) acc[nt][3] = -1e30f;
            }
        }

        // ---- online softmax (rows live on 4 lanes: shfl xor 1,2) ----
        float mx0 = -INFINITY, mx1 = -INFINITY;
#pragma unroll
        for (int nt = 0; nt < 8; nt++) {
            mx0 = fmaxf(mx0, fmaxf(acc[nt][0], acc[nt][1]));
            mx1 = fmaxf(mx1, fmaxf(acc[nt][2], acc[nt][3]));
        }
        mx0 = fmaxf(mx0, __shfl_xor_sync(0xffffffffu, mx0, 1));
        mx0 = fmaxf(mx0, __shfl_xor_sync(0xffffffffu, mx0, 2));
        mx1 = fmaxf(mx1, __shfl_xor_sync(0xffffffffu, mx1, 1));
        mx1 = fmaxf(mx1, __shfl_xor_sync(0xffffffffu, mx1, 2));

        float mn0 = fmaxf(m_[0], mx0), mn1 = fmaxf(m_[1], mx1);
        float al0 = __expf(m_[0] - mn0), al1 = __expf(m_[1] - mn1);
        m_[0] = mn0; m_[1] = mn1;

        float rs0 = 0.0f, rs1 = 0.0f;
#pragma unroll
        for (int nt = 0; nt < 8; nt++) {
            acc[nt][0] = __expf(acc[nt][0] - mn0); rs0 += acc[nt][0];
            acc[nt][1] = __expf(acc[nt][1] - mn0); rs0 += acc[nt][1];
            acc[nt][2] = __expf(acc[nt][2] - mn1); rs1 += acc[nt][2];
            acc[nt][3] = __expf(acc[nt][3] - mn1); rs1 += acc[nt][3];
        }
        rs0 += __shfl_xor_sync(0xffffffffu, rs0, 1);
        rs0 += __shfl_xor_sync(0xffffffffu, rs0, 2);
        rs1 += __shfl_xor_sync(0xffffffffu, rs1, 1);
        rs1 += __shfl_xor_sync(0xffffffffu, rs1, 2);

        l_[0] = l_[0] * al0 + rs0;
        l_[1] = l_[1] * al1 + rs1;
#pragma unroll
        for (int n = 0; n < 16; n++) {
            o_[n][0] *= al0; o_[n][1] *= al0;
            o_[n][2] *= al1; o_[n][3] *= al1;
        }

        // ---- store P into warp-private A-fragment smem ----
        {
            int pbase = w * 1024;
            int lane0 = r * 4 + (c2 & 3);
            int reg0  = 2 * (c2 >> 2);
#pragma unroll
            for (int nt = 0; nt < 8; nt++) {
                int a0 = pbase + nt * 128 + lane0 * 4 + reg0;
                Ps[a0]     = f2tf32(acc[nt][0]);
                Ps[a0 + 4] = f2tf32(acc[nt][1]);
                Ps[a0 + 1] = f2tf32(acc[nt][2]);
                Ps[a0 + 5] = f2tf32(acc[nt][3]);
            }
        }
        __syncwarp();

        // ---- O += P . V ----
        {
            int pbase = w * 1024;
#pragma unroll
            for (int ks = 0; ks < 8; ks++) {
                uint4 a = *(const uint4*)&Ps[pbase + ks * 128 + lane * 4];
#pragma unroll
                for (int nt = 0; nt < 16; nt++) {
                    uint2 b = *(const uint2*)&Vs[((ks * 16 + nt) * 32 + lane) * 2];
                    mma_tf32(o_[nt][0], o_[nt][1], o_[nt][2], o_[nt][3],
                             a.x, a.y, a.z, a.w, b.x, b.y);
                }
            }
        }
        __syncthreads();   // all warps done reading Ks/Vs before next overwrite
    }

    // ---- epilogue: normalize, write [S, HQ*D] ----
    float inv0 = 1.0f / l_[0], inv1 = 1.0f / l_[1];
#pragma unroll
    for (int nt = 0; nt < 16; nt++) {
        int col = h * D_HEAD + nt * 8 + c2;
        *(float2*)&O[(size_t)rg0 * QCOLS + col] =
            make_float2(o_[nt][0] * inv0, o_[nt][1] * inv0);
        *(float2*)&O[(size_t)rg1 * QCOLS + col] =
            make_float2(o_[nt][2] * inv1, o_[nt][3] * inv1);
    }
}

// ============================================================================
// kernel_launch
// ============================================================================
extern "C" void kernel_launch(void* const* d_in, const int* in_sizes, int n_in,
                              void* d_out, int out_size) {
    (void)in_sizes; (void)n_in; (void)out_size;
    const float* hidden = (const float*)d_in[0];
    const int*   pos    = (const int*)d_in[2];
    const float* Wq     = (const float*)d_in[3];
    const float* Wk     = (const float*)d_in[4];
    const float* Wv     = (const float*)d_in[5];
    const float* Wo     = (const float*)d_in[6];
    float* out = (float*)d_out;

    float *Qp, *Kp, *Vp, *Ap;
    cudaGetSymbolAddress((void**)&Qp, g_Q);
    cudaGetSymbolAddress((void**)&Kp, g_K);
    cudaGetSymbolAddress((void**)&Vp, g_V);
    cudaGetSymbolAddress((void**)&Ap, g_A);

    cudaFuncSetAttribute(flash_tf32,
                         cudaFuncAttributeMaxDynamicSharedMemorySize, SMEM_FA);

    dim3 blk(256);
    tf32_gemm_nt<<<dim3(QCOLS / 128, S_LEN / 128), blk>>>(hidden, Wq, Qp, S_LEN, QCOLS, HIDDEN);
    tf32_gemm_nt<<<dim3(KCOLS / 128, S_LEN / 128), blk>>>(hidden, Wk, Kp, S_LEN, KCOLS, HIDDEN);
    tf32_gemm_nt<<<dim3(KCOLS / 128, S_LEN / 128), blk>>>(hidden, Wv, Vp, S_LEN, KCOLS, HIDDEN);
    rope_kernel<<<(S_LEN * HQ * 64 + 255) / 256, 256>>>(Qp, pos, HQ, S_LEN * HQ * 64);
    rope_kernel<<<(S_LEN * HK * 64 + 255) / 256, 256>>>(Kp, pos, HK, S_LEN * HK * 64);
    // TF32 causal flash attention: 24 q-tiles x 16 heads
    flash_tf32<<<dim3(S_LEN / 128, HQ), blk, SMEM_FA>>>(Qp, Kp, Vp, Ap);
    tf32_gemm_nt<<<dim3(QCOLS / 128, S_LEN / 128), blk>>>(Ap, Wo, out, S_LEN, QCOLS, HIDDEN);
}